// round 8
// baseline (speedup 1.0000x reference)
#include <cuda_runtime.h>
#include <cstdint>

// GCNStage4_ReduceSum: out[t] += msg[e] for t = edge_index[1][e]
// msg: [NUM_EDGES, 32] f32; edge_index: [2, NUM_EDGES] int32 (harness); out: [num_nodes, 32] f32
//
// R8: ceiling-confirmed atomic scatter. Each edge row = one 128B L2 line, so
// its 8 v4 RMWs serialize on one LTS slice; 12.8M ops / 184 slices ~= 36us of
// RMW + read interference = the measured ~46us wall. This is the best-measured
// shape (R3): unroll-4, front-batched loads (MLP~8), grid-stride, coalesced
// lanes (8 lanes = one edge row), fire-and-forget red.global.add.v4.f32.

#define FEAT 32
#define UNROLL 4

__global__ void __launch_bounds__(256) scatter_add_kernel(
        const float4* __restrict__ msg4,
        const int* __restrict__ tgt,
        float* __restrict__ out,
        int num_frags)   // num_edges * 8
{
    int tid0   = blockIdx.x * blockDim.x + threadIdx.x;
    int stride = gridDim.x * blockDim.x;
    int sub    = tid0 & 7;                 // stride % 8 == 0 -> invariant across u
    int e0     = tid0 >> 3;
    int estep  = stride >> 3;

    int    t[UNROLL];
    float4 v[UNROLL];

    // Phase 1: front-batched loads (4 tgt + 4 LDG.128 in flight)
    #pragma unroll
    for (int u = 0; u < UNROLL; u++) {
        int id = tid0 + u * stride;
        if (id < num_frags) {
            int e = e0 + u * estep;
            t[u] = tgt[e];                               // broadcast across 8 lanes
            v[u] = __ldcs(&msg4[(size_t)e * 8 + sub]);   // coalesced 128B row
        }
    }

    // Phase 2: fire-and-forget vector reductions (resolve at L2)
    int off = sub * 4;
    #pragma unroll
    for (int u = 0; u < UNROLL; u++) {
        int id = tid0 + u * stride;
        if (id < num_frags) {
            float* dst = out + (size_t)t[u] * FEAT + off;
            asm volatile("red.global.add.v4.f32 [%0], {%1, %2, %3, %4};"
                         :: "l"(dst), "f"(v[u].x), "f"(v[u].y), "f"(v[u].z), "f"(v[u].w)
                         : "memory");
        }
    }
}

extern "C" void kernel_launch(void* const* d_in, const int* in_sizes, int n_in,
                              void* d_out, int out_size) {
    const float4* msg4 = (const float4*)d_in[0];
    const int*    ei   = (const int*)d_in[1];   // int32 indices
    float*        out  = (float*)d_out;

    int num_edges = in_sizes[0] / FEAT;          // 1,600,000
    const int* tgt = ei + num_edges;             // row 1 of edge_index

    // 1) zero the output (poisoned to 0xAA by harness); memset is capturable
    cudaMemsetAsync(d_out, 0, (size_t)out_size * sizeof(float));

    // 2) scatter-add: 8 lanes per edge, UNROLL fragments per thread (grid-stride)
    int num_frags = num_edges * 8;               // 12.8M
    int threads = 256;
    long long total_threads = ((long long)num_frags + UNROLL - 1) / UNROLL;
    int blocks = (int)((total_threads + threads - 1) / threads);   // 12500 exact
    scatter_add_kernel<<<blocks, threads>>>(msg4, tgt, out, num_frags);
}